// round 12
// baseline (speedup 1.0000x reference)
#include <cuda_runtime.h>

#define NN 32
#define MM 8
#define PP 16
#define BB 64
#define TT 128
#define NP1 33
#define SS 33      // shared row stride
#define QRv 0.01f

// ---------------- global scratch ----------------
__device__ float g_muf[BB][TT][NN];
__device__ float g_mup[BB][TT][NN];
__device__ float g_Sigf[BB][TT][NN][NN];
__device__ float g_Sigp[BB][TT][NN][NN];
__device__ float g_J[BB][TT][NN][NN];
__device__ float g_G[BB][TT][NN][NN];
__device__ float g_mb[BB][TT][NN];
__device__ float g_J2[BB][TT][NN][NN];
__device__ float g_G2[BB][TT][NN][NN];
__device__ float g_mb2[BB][TT][NN];
__device__ float g_J4[BB][TT][NN][NN];
__device__ float g_G4[BB][TT][NN][NN];
__device__ float g_mb4[BB][TT][NN];
__device__ float g_Sigs[BB][TT][NN][NN];
__device__ float g_mus[BB][TT][NN];
// forward-scan elements
__device__ float g_eA[BB][TT][NN][NN];
__device__ float g_eC[BB][TT][NN][NN];
__device__ float g_eJ[BB][TT][NN][NN];
__device__ float g_eb[BB][TT][NN];
__device__ float g_ee[BB][TT][NN];
__device__ float g_F2A[BB][TT][NN][NN];
__device__ float g_F2C[BB][TT][NN][NN];
__device__ float g_F2J[BB][TT][NN][NN];
__device__ float g_F2b[BB][TT][NN];
__device__ float g_F2e[BB][TT][NN];
__device__ float g_F4A[BB][TT][NN][NN];
__device__ float g_F4C[BB][TT][NN][NN];
__device__ float g_F4J[BB][TT][NN][NN];
__device__ float g_F4b[BB][TT][NN];
__device__ float g_F4e[BB][TT][NN];

// ---- helpers: 2x2-tiled 32x32 matmul (256 threads, ty=tid>>4, tx=tid&15) ----
template<bool LT, bool RT>
__device__ __forceinline__ void mm32(const float* L, const float* R, float a[4], int ty, int tx) {
    a[0] = a[1] = a[2] = a[3] = 0.f;
    #pragma unroll
    for (int k = 0; k < NN; ++k) {
        const float l0 = LT ? L[k * SS + ty]      : L[ty * SS + k];
        const float l1 = LT ? L[k * SS + ty + 16] : L[(ty + 16) * SS + k];
        const float r0 = RT ? R[tx * SS + k]      : R[k * SS + tx];
        const float r1 = RT ? R[(tx + 16) * SS + k] : R[k * SS + tx + 16];
        a[0] += l0 * r0; a[1] += l0 * r1; a[2] += l1 * r0; a[3] += l1 * r1;
    }
}
__device__ __forceinline__ void st32s(float* D, const float a[4], int ty, int tx) {
    D[ty * SS + tx] = a[0]; D[ty * SS + tx + 16] = a[1];
    D[(ty + 16) * SS + tx] = a[2]; D[(ty + 16) * SS + tx + 16] = a[3];
}
__device__ __forceinline__ void st32g(float* D, const float a[4], int ty, int tx) {
    D[ty * NN + tx] = a[0]; D[ty * NN + tx + 16] = a[1];
    D[(ty + 16) * NN + tx] = a[2]; D[(ty + 16) * NN + tx + 16] = a[3];
}

// ---- register-row Gauss-Jordan, 32 rows, 8 threads/row, CPT cols/thread ----
template<int CPT>
__device__ __forceinline__ void gj32(float* rg, int tid, float prow[2][128], float sfv[2][32]) {
    const int row = tid >> 3, c8 = tid & 7, cb = c8 * CPT;
    #pragma unroll
    for (int k = 0; k < NN; ++k) {
        const int pb = k & 1;
        if (row == k) {
            #pragma unroll
            for (int m = 0; m < CPT; ++m) prow[pb][cb + m] = rg[m];
        }
        if (c8 == k / CPT) sfv[pb][row] = rg[k - (k / CPT) * CPT];
        __syncthreads();
        const float pr = 1.0f / prow[pb][k];
        if (row == k) {
            #pragma unroll
            for (int m = 0; m < CPT; ++m) rg[m] *= pr;
        } else {
            const float f = sfv[pb][row] * pr;
            #pragma unroll
            for (int m = 0; m < CPT; ++m) rg[m] -= f * prow[pb][cb + m];
        }
    }
}

// ---- apply element (A,b,C,J,eta) to state (sSig,smu); 256 threads ----
// vv: [0:32)=b, [32:64)=eta->xm, [64:96)=v->mu'
__device__ void apply_elem(
    const float* eA, const float* eC, const float* eJ, const float* eb, const float* ee,
    float* sA, float* sC, float* sJ, float* sM, float* sXS,
    float* sSig, float* smu, float* vv,
    float prow[2][128], float sfv[2][32], int tid)
{
    const int ty = (tid >> 4) & 15, tx = tid & 15;
    for (int idx = tid; idx < NN * NN; idx += 256) {
        const int i = idx >> 5, j = idx & 31;
        sA[i * SS + j] = eA[idx]; sC[i * SS + j] = eC[idx]; sJ[i * SS + j] = eJ[idx];
    }
    if (tid < NN) vv[tid] = eb[tid];
    else if (tid < 2 * NN) vv[tid] = ee[tid - NN];
    __syncthreads();
    // M = I + Sig@J ; v = mu + Sig@eta
    {
        float a[4]; mm32<false, false>(sSig, sJ, a, ty, tx);
        if (ty == tx) { a[0] += 1.f; a[3] += 1.f; }
        st32s(sM, a, ty, tx);
    }
    if (tid < NN) {
        float s = smu[tid];
        #pragma unroll
        for (int k = 0; k < NN; ++k) s += sSig[tid * SS + k] * vv[32 + k];
        vv[64 + tid] = s;
    }
    __syncthreads();
    // GJ on [M | Sig | v]
    {
        const int row = tid >> 3, cb = (tid & 7) * 9;
        float rg[9];
        #pragma unroll
        for (int m = 0; m < 9; ++m) {
            const int col = cb + m;
            rg[m] = (col < 32) ? sM[row * SS + col]
                  : (col < 64) ? sSig[row * SS + col - 32]
                  : (col == 64) ? vv[64 + row] : 0.f;
        }
        gj32<9>(rg, tid, prow, sfv);
        #pragma unroll
        for (int m = 0; m < 9; ++m) {
            const int col = cb + m;
            if (col >= 32 && col < 64) sXS[row * SS + col - 32] = rg[m];
            else if (col == 64) vv[32 + row] = rg[m];
        }
    }
    __syncthreads();
    // T = A@XS -> sM ; mu' = A@xm + b
    {
        float a[4]; mm32<false, false>(sA, sXS, a, ty, tx);
        st32s(sM, a, ty, tx);
    }
    if (tid < NN) {
        float s = vv[tid];
        #pragma unroll
        for (int k = 0; k < NN; ++k) s += sA[tid * SS + k] * vv[32 + k];
        vv[64 + tid] = s;
    }
    __syncthreads();
    // Sig' = T@A^T + C ; mu carry
    {
        float a[4]; mm32<false, true>(sM, sA, a, ty, tx);
        a[0] += sC[ty * SS + tx];            a[1] += sC[ty * SS + tx + 16];
        a[2] += sC[(ty + 16) * SS + tx];     a[3] += sC[(ty + 16) * SS + tx + 16];
        st32s(sSig, a, ty, tx);
    }
    if (tid < NN) smu[tid] = vv[64 + tid];
    __syncthreads();
}

// ===== finit: per-step filter element, parallel over (b,t) =====
__global__ void __launch_bounds__(256) finit_kernel(
    const float* __restrict__ A, const float* __restrict__ Bm,
    const float* __restrict__ C, const float* __restrict__ U,
    const float* __restrict__ Y)
{
    const int t = blockIdx.x, b = blockIdx.y;
    const int tid = threadIdx.x;
    const int tx = tid & 15, ty = tid >> 4;
    __shared__ float sA[NN][SS], sC[PP][SS], sCA[PP][SS];
    __shared__ float sAug[PP][96];
    __shared__ float sc[NN], sy[PP];

    const float* Ab = A  + ((size_t)b * TT + t) * NN * NN;
    const float* Cb = C  + ((size_t)b * TT + t) * PP * NN;
    const float* Bb = Bm + ((size_t)b * TT + t) * NN * MM;
    const float* Ub = U  + ((size_t)b * TT + t) * MM;
    const float* Yb = Y  + ((size_t)b * TT + t) * PP;

    for (int idx = tid; idx < NN * NN; idx += 256) sA[idx >> 5][idx & 31] = Ab[idx];
    for (int idx = tid; idx < PP * NN; idx += 256) sC[idx >> 5][idx & 31] = Cb[idx];
    if (tid < NN) {
        float m = 0.f;
        #pragma unroll
        for (int k = 0; k < MM; ++k) m += Bb[tid * MM + k] * Ub[k];
        sc[tid] = m;
    }
    if (tid >= 32 && tid < 32 + PP) sy[tid - 32] = Yb[tid - 32];
    __syncthreads();
    // CA, Aug = [S | C | CA | d]
    {
        float ca0 = 0.f, ca1 = 0.f, s = 0.f;
        #pragma unroll
        for (int k = 0; k < NN; ++k) {
            const float cv = sC[ty][k];
            ca0 += cv * sA[k][tx]; ca1 += cv * sA[k][tx + 16];
            s   += cv * sC[tx][k];
        }
        sCA[ty][tx] = ca0; sCA[ty][tx + 16] = ca1;
        sAug[ty][48 + tx] = ca0; sAug[ty][48 + tx + 16] = ca1;
        sAug[ty][16 + tx] = sC[ty][tx]; sAug[ty][16 + tx + 16] = sC[ty][tx + 16];
        sAug[ty][tx] = QRv * s + ((ty == tx) ? QRv : 0.f);
    }
    if (tid < PP) {
        float dd = sy[tid];
        #pragma unroll
        for (int k = 0; k < NN; ++k) dd -= sC[tid][k] * sc[k];
        sAug[tid][80] = dd;
    }
    __syncthreads();
    // 16-row GJ on 16x81
    {
        const int r = tid >> 4, c = tid & 15;
        #pragma unroll
        for (int k = 0; k < PP; ++k) {
            const float pr = 1.0f / sAug[k][k];
            const float f  = sAug[r][k];
            float rk[6], vvv[6];
            #pragma unroll
            for (int m = 0; m < 6; ++m) {
                const int col = c + 16 * m;
                if (col < 81) { rk[m] = sAug[k][col]; vvv[m] = sAug[r][col]; }
            }
            __syncthreads();
            #pragma unroll
            for (int m = 0; m < 6; ++m) {
                const int col = c + 16 * m;
                if (col < 81) sAug[r][col] = (r == k) ? rk[m] * pr : vvv[m] - f * pr * rk[m];
            }
            __syncthreads();
        }
    }
    // outputs
    {
        float a00 = sA[ty][tx],      a01 = sA[ty][tx + 16];
        float a10 = sA[ty + 16][tx], a11 = sA[ty + 16][tx + 16];
        float c00 = 0.f, c01 = 0.f, c10 = 0.f, c11 = 0.f;
        float j00 = 0.f, j01 = 0.f, j10 = 0.f, j11 = 0.f;
        #pragma unroll
        for (int k = 0; k < PP; ++k) {
            const float ci0 = sC[k][ty],  ci1 = sC[k][ty + 16];
            const float qi0 = sCA[k][ty], qi1 = sCA[k][ty + 16];
            const float sa0 = sAug[k][48 + tx], sa1 = sAug[k][48 + tx + 16];
            const float sb0 = sAug[k][16 + tx], sb1 = sAug[k][16 + tx + 16];
            a00 -= QRv * ci0 * sa0; a01 -= QRv * ci0 * sa1;
            a10 -= QRv * ci1 * sa0; a11 -= QRv * ci1 * sa1;
            c00 += ci0 * sb0; c01 += ci0 * sb1; c10 += ci1 * sb0; c11 += ci1 * sb1;
            j00 += qi0 * sa0; j01 += qi0 * sa1; j10 += qi1 * sa0; j11 += qi1 * sa1;
        }
        float* eA = &g_eA[b][t][0][0];
        eA[ty * NN + tx] = a00;        eA[ty * NN + tx + 16] = a01;
        eA[(ty + 16) * NN + tx] = a10; eA[(ty + 16) * NN + tx + 16] = a11;
        float* eC = &g_eC[b][t][0][0];
        eC[ty * NN + tx]             = ((ty == tx) ? QRv : 0.f) - QRv * QRv * c00;
        eC[ty * NN + tx + 16]        = -QRv * QRv * c01;
        eC[(ty + 16) * NN + tx]      = -QRv * QRv * c10;
        eC[(ty + 16) * NN + tx + 16] = ((ty == tx) ? QRv : 0.f) - QRv * QRv * c11;
        float* eJ = &g_eJ[b][t][0][0];
        eJ[ty * NN + tx] = j00;        eJ[ty * NN + tx + 16] = j01;
        eJ[(ty + 16) * NN + tx] = j10; eJ[(ty + 16) * NN + tx + 16] = j11;
    }
    if (tid < NN) {
        float bb = sc[tid], ee = 0.f;
        #pragma unroll
        for (int k = 0; k < PP; ++k) {
            const float sd = sAug[k][80];
            bb += QRv * sC[k][tid] * sd;
            ee += sCA[k][tid] * sd;
        }
        g_eb[b][t][tid] = bb;
        g_ee[b][t][tid] = ee;
    }
}

// ===== fcompose: e1 (earlier, at ti) composed-with e2 (at t) -> dst at t =====
__global__ void __launch_bounds__(256) fcompose_kernel(int mode)
{
    const int b = blockIdx.y;
    const int t  = mode ? 4 * blockIdx.x + 3 : 2 * blockIdx.x + 1;
    const int ti = mode ? t - 2 : t - 1;
    const int tid = threadIdx.x;
    const int ty = tid >> 4, tx = tid & 15;
    __shared__ float sA1[NN][SS], sA2[NN][SS], sC1[NN][SS], sJ2[NN][SS];
    __shared__ float sX[NN][SS], sXC[NN][SS], sY[NN][SS];
    __shared__ float prow[2][128], sfv[2][32];
    __shared__ float vv[128];

    const float *pA1, *pC1, *pJ1, *pb1, *pe1, *pA2, *pC2, *pJ2a, *pb2, *pe2;
    float *dA, *dC, *dJ, *db, *de;
    if (mode) {
        pA1 = &g_F2A[b][ti][0][0]; pC1 = &g_F2C[b][ti][0][0]; pJ1 = &g_F2J[b][ti][0][0];
        pb1 = g_F2b[b][ti]; pe1 = g_F2e[b][ti];
        pA2 = &g_F2A[b][t][0][0]; pC2 = &g_F2C[b][t][0][0]; pJ2a = &g_F2J[b][t][0][0];
        pb2 = g_F2b[b][t]; pe2 = g_F2e[b][t];
        dA = &g_F4A[b][t][0][0]; dC = &g_F4C[b][t][0][0]; dJ = &g_F4J[b][t][0][0];
        db = g_F4b[b][t]; de = g_F4e[b][t];
    } else {
        pA1 = &g_eA[b][ti][0][0]; pC1 = &g_eC[b][ti][0][0]; pJ1 = &g_eJ[b][ti][0][0];
        pb1 = g_eb[b][ti]; pe1 = g_ee[b][ti];
        pA2 = &g_eA[b][t][0][0]; pC2 = &g_eC[b][t][0][0]; pJ2a = &g_eJ[b][t][0][0];
        pb2 = g_eb[b][t]; pe2 = g_ee[b][t];
        dA = &g_F2A[b][t][0][0]; dC = &g_F2C[b][t][0][0]; dJ = &g_F2J[b][t][0][0];
        db = g_F2b[b][t]; de = g_F2e[b][t];
    }
    for (int idx = tid; idx < NN * NN; idx += 256) {
        const int i = idx >> 5, j = idx & 31;
        sA1[i][j] = pA1[idx]; sA2[i][j] = pA2[idx];
        sC1[i][j] = pC1[idx]; sJ2[i][j] = pJ2a[idx];
    }
    if (tid < NN) vv[tid] = pb1[tid];
    else if (tid < 2 * NN) vv[tid] = pe2[tid - NN];
    __syncthreads();
    // W = I + C1@J2 -> sX ; u = b1 + C1@eta2 -> vv[96:]
    {
        float a[4]; mm32<false, false>(&sC1[0][0], &sJ2[0][0], a, ty, tx);
        if (ty == tx) { a[0] += 1.f; a[3] += 1.f; }
        st32s(&sX[0][0], a, ty, tx);
    }
    if (tid < NN) {
        float s = vv[tid];
        #pragma unroll
        for (int k = 0; k < NN; ++k) s += sC1[tid][k] * vv[32 + k];
        vv[96 + tid] = s;
    }
    __syncthreads();
    // GJ on [W | A1 | C1 | u]
    {
        const int row = tid >> 3, cb = (tid & 7) * 13;
        float rg[13];
        #pragma unroll
        for (int m = 0; m < 13; ++m) {
            const int col = cb + m;
            rg[m] = (col < 32) ? sX[row][col]
                  : (col < 64) ? sA1[row][col - 32]
                  : (col < 96) ? sC1[row][col - 64]
                  : (col == 96) ? vv[96 + row] : 0.f;
        }
        gj32<13>(rg, tid, prow, sfv);
        #pragma unroll
        for (int m = 0; m < 13; ++m) {
            const int col = cb + m;
            if (col >= 32 && col < 64) sX[row][col - 32] = rg[m];        // XA
            else if (col >= 64 && col < 96) sXC[row][col - 64] = rg[m];  // XC
            else if (col == 96) vv[96 + row] = rg[m];                    // xu
        }
    }
    __syncthreads();
    // dA = A2@XA ; sY = J2@XA ; db = A2@xu + b2 ; w = eta2 - J2@b1 -> vv[64:96]
    {
        float a[4]; mm32<false, false>(&sA2[0][0], &sX[0][0], a, ty, tx);
        st32g(dA, a, ty, tx);
    }
    {
        float a[4]; mm32<false, false>(&sJ2[0][0], &sX[0][0], a, ty, tx);
        st32s(&sY[0][0], a, ty, tx);
    }
    if (tid < NN) {
        float s = pb2[tid];
        #pragma unroll
        for (int k = 0; k < NN; ++k) s += sA2[tid][k] * vv[96 + k];
        db[tid] = s;
    } else if (tid < 2 * NN) {
        const int i = tid - NN;
        float s = vv[32 + i];
        #pragma unroll
        for (int k = 0; k < NN; ++k) s -= sJ2[i][k] * vv[k];
        vv[64 + i] = s;
    }
    __syncthreads();
    // dJ = A1^T@Y + J1 ; T = A2@XC -> sX ; z = XC@w -> vv[96:]
    {
        float a[4]; mm32<true, false>(&sA1[0][0], &sY[0][0], a, ty, tx);
        a[0] += pJ1[ty * NN + tx];            a[1] += pJ1[ty * NN + tx + 16];
        a[2] += pJ1[(ty + 16) * NN + tx];     a[3] += pJ1[(ty + 16) * NN + tx + 16];
        st32g(dJ, a, ty, tx);
    }
    {
        float a[4]; mm32<false, false>(&sA2[0][0], &sXC[0][0], a, ty, tx);
        st32s(&sX[0][0], a, ty, tx);
    }
    if (tid < NN) {
        float s = 0.f;
        #pragma unroll
        for (int k = 0; k < NN; ++k) s += sXC[tid][k] * vv[64 + k];
        vv[96 + tid] = s;
    }
    __syncthreads();
    // dC = T@A2^T + C2 ; w2 = w - J2@z -> vv[0:32]
    {
        float a[4]; mm32<false, true>(&sX[0][0], &sA2[0][0], a, ty, tx);
        a[0] += pC2[ty * NN + tx];            a[1] += pC2[ty * NN + tx + 16];
        a[2] += pC2[(ty + 16) * NN + tx];     a[3] += pC2[(ty + 16) * NN + tx + 16];
        st32g(dC, a, ty, tx);
    }
    if (tid < NN) {
        float s = vv[64 + tid];
        #pragma unroll
        for (int k = 0; k < NN; ++k) s -= sJ2[tid][k] * vv[96 + k];
        vv[tid] = s;
    }
    __syncthreads();
    // de = A1^T@w2 + e1
    if (tid < NN) {
        float s = pe1[tid];
        #pragma unroll
        for (int k = 0; k < NN; ++k) s += sA1[k][tid] * vv[k];
        de[tid] = s;
    }
}

// ===== fserial: 32 steps applying F4 elements; 1 CTA / batch =====
__global__ void __launch_bounds__(256) fserial_kernel(
    const float* __restrict__ mu0, const float* __restrict__ Sigma0)
{
    const int b = blockIdx.x;
    const int tid = threadIdx.x;
    __shared__ float sA[NN][SS], sC[NN][SS], sJ[NN][SS], sM[NN][SS], sXS[NN][SS], sSig[NN][SS];
    __shared__ float smu[NN], vv[96];
    __shared__ float prow[2][128], sfv[2][32];

    for (int idx = tid; idx < NN * NN; idx += 256) sSig[idx >> 5][idx & 31] = Sigma0[idx];
    if (tid < NN) smu[tid] = mu0[tid];
    __syncthreads();
    for (int v = 0; v < 32; ++v) {
        const int t = 4 * v + 3;
        apply_elem(&g_F4A[b][t][0][0], &g_F4C[b][t][0][0], &g_F4J[b][t][0][0],
                   g_F4b[b][t], g_F4e[b][t],
                   &sA[0][0], &sC[0][0], &sJ[0][0], &sM[0][0], &sXS[0][0],
                   &sSig[0][0], smu, vv, prow, sfv, tid);
        for (int idx = tid; idx < NN * NN; idx += 256)
            g_Sigf[b][t][idx >> 5][idx & 31] = sSig[idx >> 5][idx & 31];
        if (tid < NN) g_muf[b][t][tid] = smu[tid];
        __syncthreads();
    }
}

// ===== ffill: mode0: t=4w+1 via F2 (prev=t-2); mode1: t=2w via e (prev=t-1) =====
__global__ void __launch_bounds__(256) ffill_kernel(
    const float* __restrict__ mu0, const float* __restrict__ Sigma0, int mode)
{
    const int b = blockIdx.y, w = blockIdx.x;
    const int t = mode ? 2 * w : 4 * w + 1;
    const int pv = mode ? t - 1 : t - 2;
    const int tid = threadIdx.x;
    __shared__ float sA[NN][SS], sC[NN][SS], sJ[NN][SS], sM[NN][SS], sXS[NN][SS], sSig[NN][SS];
    __shared__ float smu[NN], vv[96];
    __shared__ float prow[2][128], sfv[2][32];

    for (int idx = tid; idx < NN * NN; idx += 256) {
        const int i = idx >> 5, j = idx & 31;
        sSig[i][j] = (pv < 0) ? Sigma0[idx] : g_Sigf[b][pv][i][j];
    }
    if (tid < NN) smu[tid] = (pv < 0) ? mu0[tid] : g_muf[b][pv][tid];
    __syncthreads();
    const float* eA = mode ? &g_eA[b][t][0][0] : &g_F2A[b][t][0][0];
    const float* eC = mode ? &g_eC[b][t][0][0] : &g_F2C[b][t][0][0];
    const float* eJ = mode ? &g_eJ[b][t][0][0] : &g_F2J[b][t][0][0];
    const float* eb = mode ? g_eb[b][t] : g_F2b[b][t];
    const float* ee = mode ? g_ee[b][t] : g_F2e[b][t];
    apply_elem(eA, eC, eJ, eb, ee,
               &sA[0][0], &sC[0][0], &sJ[0][0], &sM[0][0], &sXS[0][0],
               &sSig[0][0], smu, vv, prow, sfv, tid);
    for (int idx = tid; idx < NN * NN; idx += 256)
        g_Sigf[b][t][idx >> 5][idx & 31] = sSig[idx >> 5][idx & 31];
    if (tid < NN) g_muf[b][t][tid] = smu[tid];
}

// ===== sigp: Sigp_t = A Sigf_{t-1} A^T + qI ; mup_t = A muf_{t-1} + B u =====
__global__ void __launch_bounds__(256) sigp_kernel(
    const float* __restrict__ A, const float* __restrict__ Bm,
    const float* __restrict__ U,
    const float* __restrict__ mu0, const float* __restrict__ Sigma0)
{
    const int t = blockIdx.x, b = blockIdx.y;
    const int tid = threadIdx.x;
    const int ty = tid >> 4, tx = tid & 15;
    __shared__ float sA[NN][SS], sSig[NN][SS], sT[NN][SS];
    __shared__ float smu[NN];

    const float* Ab = A + ((size_t)b * TT + t) * NN * NN;
    for (int idx = tid; idx < NN * NN; idx += 256) {
        const int i = idx >> 5, j = idx & 31;
        sA[i][j] = Ab[idx];
        sSig[i][j] = (t == 0) ? Sigma0[idx] : g_Sigf[b][t - 1][i][j];
    }
    if (tid < NN) smu[tid] = (t == 0) ? mu0[tid] : g_muf[b][t - 1][tid];
    __syncthreads();
    {
        float a[4]; mm32<false, false>(&sA[0][0], &sSig[0][0], a, ty, tx);
        st32s(&sT[0][0], a, ty, tx);
    }
    if (tid < NN) {
        const float* Bb = Bm + ((size_t)b * TT + t) * NN * MM;
        const float* Ub = U  + ((size_t)b * TT + t) * MM;
        float m = 0.f;
        #pragma unroll
        for (int k = 0; k < NN; ++k) m += sA[tid][k] * smu[k];
        #pragma unroll
        for (int k = 0; k < MM; ++k) m += Bb[tid * MM + k] * Ub[k];
        g_mup[b][t][tid] = m;
    }
    __syncthreads();
    {
        float a[4]; mm32<false, true>(&sT[0][0], &sA[0][0], a, ty, tx);
        if (ty == tx) { a[0] += QRv; a[3] += QRv; }
        st32g(&g_Sigp[b][t][0][0], a, ty, tx);
    }
}

// ===== smoother gains + backward constants (unchanged, proven) =====
__global__ void __launch_bounds__(256) jgain_kernel(const float* __restrict__ A)
{
    const int t = blockIdx.x;
    const int b = blockIdx.y;
    const int tid = threadIdx.x;
    const int tx = tid & 15, ty = tid >> 4;
    __shared__ float sSf[NN][SS], sA[NN][SS], sX[NN][SS], sT2[NN][SS];
    __shared__ float prow[2][2 * NN];
    __shared__ float sf[2][NN];
    __shared__ float smp1[NN];

    const float* Ab = A + ((size_t)b * TT + t) * NN * NN;
    for (int idx = tid; idx < NN * NN; idx += 256) {
        sSf[idx >> 5][idx & 31] = g_Sigf[b][t][idx >> 5][idx & 31];
        sA[idx >> 5][idx & 31]  = Ab[idx];
    }
    if (tid < NN) smp1[tid] = g_mup[b][t + 1][tid];
    __syncthreads();
    {
        float a[4]; mm32<false, true>(&sSf[0][0], &sA[0][0], a, ty, tx);
        st32s(&sX[0][0], a, ty, tx);
    }
    __syncthreads();
    const int row = tid >> 3;
    const int c0  = (tid & 7) * 8;
    float r8[8];
    if (c0 < NN) {
        #pragma unroll
        for (int m = 0; m < 8; ++m) r8[m] = g_Sigp[b][t + 1][row][c0 + m];
    } else {
        #pragma unroll
        for (int m = 0; m < 8; ++m) r8[m] = sX[c0 - NN + m][row];
    }
    #pragma unroll
    for (int k = 0; k < NN; ++k) {
        const int pb = k & 1;
        if (row == k) {
            #pragma unroll
            for (int m = 0; m < 8; ++m) prow[pb][c0 + m] = r8[m];
        }
        if ((tid & 7) == (k >> 3)) sf[pb][row] = r8[k & 7];
        __syncthreads();
        const float pr = 1.0f / prow[pb][k];
        if (row == k) {
            #pragma unroll
            for (int m = 0; m < 8; ++m) r8[m] *= pr;
        } else {
            const float g = sf[pb][row] * pr;
            #pragma unroll
            for (int m = 0; m < 8; ++m) r8[m] -= g * prow[pb][c0 + m];
        }
    }
    __syncthreads();
    if (c0 >= NN) {
        #pragma unroll
        for (int m = 0; m < 8; ++m) sX[c0 - NN + m][row] = r8[m];   // J
    }
    __syncthreads();
    for (int idx = tid; idx < NN * NN; idx += 256) {
        g_J[b][t][idx >> 5][idx & 31] = sX[idx >> 5][idx & 31];
        sA[idx >> 5][idx & 31] = g_Sigp[b][t + 1][idx >> 5][idx & 31];
    }
    __syncthreads();
    {
        float a[4]; mm32<false, false>(&sX[0][0], &sA[0][0], a, ty, tx);
        st32s(&sT2[0][0], a, ty, tx);
    }
    __syncthreads();
    {
        float a[4]; mm32<false, true>(&sT2[0][0], &sX[0][0], a, ty, tx);
        float* gg = &g_G[b][t][0][0];
        gg[ty * NN + tx]             = sSf[ty][tx]           - a[0];
        gg[ty * NN + tx + 16]        = sSf[ty][tx + 16]      - a[1];
        gg[(ty + 16) * NN + tx]      = sSf[ty + 16][tx]      - a[2];
        gg[(ty + 16) * NN + tx + 16] = sSf[ty + 16][tx + 16] - a[3];
    }
    if (tid < NN) {
        float m = g_muf[b][t][tid];
        #pragma unroll
        for (int k = 0; k < NN; ++k) m -= sX[tid][k] * smp1[k];
        g_mb[b][t][tid] = m;
    }
}

// ===== pairK: mode0 stride-1->2 (t=2bx+1); mode1 stride-2->4 (t=4bx+3) =====
__global__ void __launch_bounds__(256) pairK_kernel(int mode)
{
    const int b = blockIdx.y;
    const int t = mode ? 4 * blockIdx.x + 3 : 2 * blockIdx.x + 1;
    const int dt = mode ? 2 : 1;
    const int tid = threadIdx.x;
    const int tx = tid & 15, ty = tid >> 4;
    __shared__ float sJ[NN][SS], sJn[NN][SS], sGn[NN][SS], sT[NN][SS];
    __shared__ float smbn[NN];

    const float* pJ  = mode ? &g_J2[b][t][0][0]      : &g_J[b][t][0][0];
    const float* pJn = mode ? &g_J2[b][t + dt][0][0] : &g_J[b][t + dt][0][0];
    const float* pGn = mode ? &g_G2[b][t + dt][0][0] : &g_G[b][t + dt][0][0];
    const float* pG  = mode ? &g_G2[b][t][0][0]      : &g_G[b][t][0][0];
    const float* pmb  = mode ? g_mb2[b][t]      : g_mb[b][t];
    const float* pmbn = mode ? g_mb2[b][t + dt] : g_mb[b][t + dt];
    float* dJ = mode ? &g_J4[b][t][0][0] : &g_J2[b][t][0][0];
    float* dG = mode ? &g_G4[b][t][0][0] : &g_G2[b][t][0][0];
    float* dmb = mode ? g_mb4[b][t] : g_mb2[b][t];

    for (int idx = tid; idx < NN * NN; idx += 256) {
        const int i = idx >> 5, j = idx & 31;
        sJ[i][j] = pJ[idx]; sJn[i][j] = pJn[idx]; sGn[i][j] = pGn[idx];
    }
    if (tid < NN) smbn[tid] = pmbn[tid];
    __syncthreads();
    {
        float a[4]; mm32<false, false>(&sJ[0][0], &sJn[0][0], a, ty, tx);
        st32g(dJ, a, ty, tx);
    }
    {
        float a[4]; mm32<false, false>(&sJ[0][0], &sGn[0][0], a, ty, tx);
        st32s(&sT[0][0], a, ty, tx);
    }
    if (tid < NN) {
        float m = pmb[tid];
        #pragma unroll
        for (int k = 0; k < NN; ++k) m += sJ[tid][k] * smbn[k];
        dmb[tid] = m;
    }
    __syncthreads();
    {
        float a[4]; mm32<false, true>(&sT[0][0], &sJ[0][0], a, ty, tx);
        dG[ty * NN + tx]             = pG[ty * NN + tx]             + a[0];
        dG[ty * NN + tx + 16]        = pG[ty * NN + tx + 16]        + a[1];
        dG[(ty + 16) * NN + tx]      = pG[(ty + 16) * NN + tx]      + a[2];
        dG[(ty + 16) * NN + tx + 16] = pG[(ty + 16) * NN + tx + 16] + a[3];
    }
}

// ===== serial backward with stride-4 ops: 31 steps =====
__global__ void __launch_bounds__(512) bwd4_kernel(float* __restrict__ out)
{
    const int b = blockIdx.x;
    const int tid = threadIdx.x;
    const int j  = tid & 31;
    const int i0 = tid >> 5;
    __shared__ float sJ[2][NN][SS], sTmp[NN][SS], sSig[NN][SS];
    __shared__ float smu[NN];

    {
        const float v0 = g_Sigf[b][TT - 1][i0][j];
        const float v1 = g_Sigf[b][TT - 1][i0 + 16][j];
        sSig[i0][j] = v0; sSig[i0 + 16][j] = v1;
        g_Sigs[b][TT - 1][i0][j] = v0; g_Sigs[b][TT - 1][i0 + 16][j] = v1;
        const size_t base = ((size_t)b * TT + (TT - 1)) * NN;
        out[(base + i0) * NP1 + 1 + j] = v0;
        out[(base + i0 + 16) * NP1 + 1 + j] = v1;
        if (tid < NN) {
            const float m = g_muf[b][TT - 1][tid];
            smu[tid] = m;
            g_mus[b][TT - 1][tid] = m;
            out[(base + tid) * NP1] = m;
        }
    }
    float pG0 = g_G4[b][123][i0][j];
    float pG1 = g_G4[b][123][i0 + 16][j];
    sJ[0][i0][j]      = g_J4[b][123][i0][j];
    sJ[0][i0 + 16][j] = g_J4[b][123][i0 + 16][j];
    __syncthreads();
    int cur = 0;
    for (int v = 30; v >= 0; --v) {
        const int t = 4 * v + 3;
        float a0 = 0.f, a1 = 0.f;
        #pragma unroll
        for (int k = 0; k < NN; ++k) {
            const float r = sSig[k][j];
            a0 += sJ[cur][i0][k] * r; a1 += sJ[cur][i0 + 16][k] * r;
        }
        sTmp[i0][j] = a0; sTmp[i0 + 16][j] = a1;
        float m = 0.f;
        if (tid < NN) {
            m = g_mb4[b][t][tid];
            #pragma unroll
            for (int k = 0; k < NN; ++k) m += sJ[cur][tid][k] * smu[k];
        }
        float nJ0 = 0.f, nJ1 = 0.f, nG0 = 0.f, nG1 = 0.f;
        if (v > 0) {
            nJ0 = g_J4[b][t - 4][i0][j];     nJ1 = g_J4[b][t - 4][i0 + 16][j];
            nG0 = g_G4[b][t - 4][i0][j];     nG1 = g_G4[b][t - 4][i0 + 16][j];
        }
        __syncthreads();
        {
            float e0 = 0.f, e1 = 0.f;
            #pragma unroll
            for (int k = 0; k < NN; ++k) {
                const float jj = sJ[cur][j][k];
                e0 += sTmp[i0][k] * jj; e1 += sTmp[i0 + 16][k] * jj;
            }
            const float v0 = pG0 + e0;
            const float v1 = pG1 + e1;
            sSig[i0][j] = v0; sSig[i0 + 16][j] = v1;
            g_Sigs[b][t][i0][j] = v0; g_Sigs[b][t][i0 + 16][j] = v1;
            const size_t base = ((size_t)b * TT + t) * NN;
            out[(base + i0) * NP1 + 1 + j] = v0;
            out[(base + i0 + 16) * NP1 + 1 + j] = v1;
            if (tid < NN) {
                smu[tid] = m;
                g_mus[b][t][tid] = m;
                out[(base + tid) * NP1] = m;
            }
        }
        if (v > 0) {
            sJ[cur ^ 1][i0][j] = nJ0; sJ[cur ^ 1][i0 + 16][j] = nJ1;
            pG0 = nG0; pG1 = nG1;
        }
        __syncthreads();
        cur ^= 1;
    }
}

// ===== fillK: mode0: t=4bx+1 via stride-2 (src t+2); mode1: t=2bx via stride-1 (src t+1) =====
__global__ void __launch_bounds__(256) fillK_kernel(float* __restrict__ out, int mode)
{
    const int b = blockIdx.y;
    const int t = mode ? 2 * blockIdx.x : 4 * blockIdx.x + 1;
    const int dt = mode ? 1 : 2;
    const int tid = threadIdx.x;
    const int tx = tid & 15, ty = tid >> 4;
    __shared__ float sJ[NN][SS], sS[NN][SS], sT[NN][SS];
    __shared__ float smun[NN];

    const float* pJ = mode ? &g_J[b][t][0][0] : &g_J2[b][t][0][0];
    const float* pG = mode ? &g_G[b][t][0][0] : &g_G2[b][t][0][0];
    const float* pmb = mode ? g_mb[b][t] : g_mb2[b][t];
    for (int idx = tid; idx < NN * NN; idx += 256) {
        const int i = idx >> 5, j = idx & 31;
        sJ[i][j] = pJ[idx];
        sS[i][j] = g_Sigs[b][t + dt][i][j];
    }
    if (tid < NN) smun[tid] = g_mus[b][t + dt][tid];
    __syncthreads();
    {
        float a[4]; mm32<false, false>(&sJ[0][0], &sS[0][0], a, ty, tx);
        st32s(&sT[0][0], a, ty, tx);
    }
    __syncthreads();
    {
        float a[4]; mm32<false, true>(&sT[0][0], &sJ[0][0], a, ty, tx);
        const float v00 = pG[ty * NN + tx]             + a[0];
        const float v01 = pG[ty * NN + tx + 16]        + a[1];
        const float v10 = pG[(ty + 16) * NN + tx]      + a[2];
        const float v11 = pG[(ty + 16) * NN + tx + 16] + a[3];
        if (!mode) {
            g_Sigs[b][t][ty][tx] = v00;      g_Sigs[b][t][ty][tx + 16] = v01;
            g_Sigs[b][t][ty + 16][tx] = v10; g_Sigs[b][t][ty + 16][tx + 16] = v11;
        }
        const size_t base = ((size_t)b * TT + t) * NN;
        out[(base + ty) * NP1 + 1 + tx]           = v00;
        out[(base + ty) * NP1 + 1 + tx + 16]      = v01;
        out[(base + ty + 16) * NP1 + 1 + tx]      = v10;
        out[(base + ty + 16) * NP1 + 1 + tx + 16] = v11;
    }
    if (tid < NN) {
        float m = pmb[tid];
        #pragma unroll
        for (int k = 0; k < NN; ++k) m += sJ[tid][k] * smun[k];
        if (!mode) g_mus[b][t][tid] = m;
        out[(((size_t)b * TT + t) * NN + tid) * NP1] = m;
    }
}

// ---------------- launch ----------------
extern "C" void kernel_launch(void* const* d_in, const int* in_sizes, int n_in,
                              void* d_out, int out_size)
{
    const float* Y      = (const float*)d_in[0];
    const float* U      = (const float*)d_in[1];
    const float* A      = (const float*)d_in[2];
    const float* Bm     = (const float*)d_in[3];
    const float* C      = (const float*)d_in[4];
    const float* mu0    = (const float*)d_in[5];
    const float* Sigma0 = (const float*)d_in[6];
    float* out = (float*)d_out;

    finit_kernel<<<dim3(TT, BB), 256>>>(A, Bm, C, U, Y);
    fcompose_kernel<<<dim3(64, BB), 256>>>(0);
    fcompose_kernel<<<dim3(32, BB), 256>>>(1);
    fserial_kernel<<<BB, 256>>>(mu0, Sigma0);
    ffill_kernel<<<dim3(32, BB), 256>>>(mu0, Sigma0, 0);
    ffill_kernel<<<dim3(64, BB), 256>>>(mu0, Sigma0, 1);
    sigp_kernel<<<dim3(TT, BB), 256>>>(A, Bm, U, mu0, Sigma0);
    jgain_kernel<<<dim3(TT - 1, BB), 256>>>(A);
    pairK_kernel<<<dim3(63, BB), 256>>>(0);
    pairK_kernel<<<dim3(31, BB), 256>>>(1);
    bwd4_kernel<<<BB, 512>>>(out);
    fillK_kernel<<<dim3(32, BB), 256>>>(out, 0);
    fillK_kernel<<<dim3(64, BB), 256>>>(out, 1);
}